// round 4
// baseline (speedup 1.0000x reference)
#include <cuda_runtime.h>
#include <math.h>
#include <stdint.h>

#define Bn 4
#define Tn 8
#define Hn 256
#define Wn 256
#define Nn (Bn*Tn*Hn*Wn)   // 2,097,152

// params layout: 0:cc 1:ce 2:cw 3:cs 4:cn 5:cx(corner) 6:D
__device__ float g_params[7 * Nn];
__device__ float g_partLogD[1024];   // conv blocks
__device__ float g_partXQX[2048];    // fused stencil blocks

__device__ __forceinline__ uint64_t pack2(float lo, float hi) {
    uint64_t r; asm("mov.b64 %0, {%1,%2};" : "=l"(r) : "f"(lo), "f"(hi)); return r;
}
__device__ __forceinline__ uint64_t ffma2(uint64_t a, uint64_t b, uint64_t c) {
    uint64_t d; asm("fma.rn.f32x2 %0, %1, %2, %3;" : "=l"(d) : "l"(a), "l"(b), "l"(c)); return d;
}
__device__ __forceinline__ void unpack2(uint64_t v, float& lo, float& hi) {
    asm("mov.b64 {%0,%1}, %2;" : "=f"(lo), "=f"(hi) : "l"(v));
}

__device__ __forceinline__ float block_reduce_sum(float v) {
    __shared__ float red[8];
    #pragma unroll
    for (int o = 16; o > 0; o >>= 1) v += __shfl_down_sync(0xffffffffu, v, o);
    int lane = threadIdx.x & 31, wid = threadIdx.x >> 5;
    if (lane == 0) red[wid] = v;
    __syncthreads();
    if (wid == 0) {
        v = (lane < 8) ? red[lane] : 0.f;
        #pragma unroll
        for (int o = 4; o > 0; o >>= 1) v += __shfl_down_sync(0xffffffffu, v, o);
    }
    return v;  // valid on thread 0
}

// ---------------------------------------------------------------------------
// Conv 3x3 (8 -> 64 ch) via f32x2 row-pair FMAs, duplicated weights in smem.
// Block: 256 threads, 32x32 output tile, 2 t-values per CTA.
// grid (8, 8, Bn*4) = 1024 CTAs.
// ---------------------------------------------------------------------------
__global__ __launch_bounds__(256, 3)
void conv_kernel(const float* __restrict__ x, const float* __restrict__ w) {
    __shared__ float xs[8][34][34];
    __shared__ __align__(16) uint64_t ws2[72][8];   // (w,w) pairs, [k][g]

    const int tid = threadIdx.x;
    const int tx  = tid & 31;
    const int ty  = tid >> 5;
    const int b   = blockIdx.z >> 2;
    const int t0  = (blockIdx.z & 3) * 2;
    const int h0  = blockIdx.y * 32;
    const int w0  = blockIdx.x * 32;

    const float* xb = x + b * Tn * Hn * Wn;
    for (int i = tid; i < 8 * 34 * 34; i += 256) {
        int ic  = i / 1156;
        int rem = i - ic * 1156;
        int ly  = rem / 34;
        int lx  = rem - ly * 34;
        int gh  = h0 - 1 + ly;
        int gw  = w0 - 1 + lx;
        float v = 0.f;
        if ((unsigned)gh < (unsigned)Hn && (unsigned)gw < (unsigned)Wn)
            v = xb[(ic * Hn + gh) * Wn + gw];
        xs[ic][ly][lx] = v;
    }

    float local_logD = 0.f;

    #pragma unroll 1
    for (int tt = t0; tt < t0 + 2; ++tt) {
        __syncthreads();
        for (int j = tid; j < 576; j += 256) {
            int k = j >> 3;
            int g = j & 7;
            float v = w[(g * 8 + tt) * 72 + k];
            ws2[k][g] = pack2(v, v);
        }
        __syncthreads();

        // acc01[g] holds rows (0,1); acc23[g] holds rows (2,3)
        uint64_t acc01[8], acc23[8];
        #pragma unroll
        for (int g = 0; g < 8; ++g) { acc01[g] = 0; acc23[g] = 0; }

        #pragma unroll 1
        for (int ic = 0; ic < 8; ++ic) {
            // 6x3 x-window in registers
            float xv[6][3];
            #pragma unroll
            for (int rr = 0; rr < 6; ++rr)
                #pragma unroll
                for (int cc = 0; cc < 3; ++cc)
                    xv[rr][cc] = xs[ic][ty * 4 + rr][tx + cc];

            #pragma unroll
            for (int kh = 0; kh < 3; ++kh) {
                #pragma unroll
                for (int kw = 0; kw < 3; ++kw) {
                    const int k = ic * 9 + kh * 3 + kw;
                    uint64_t xp01 = pack2(xv[kh + 0][kw], xv[kh + 1][kw]);
                    uint64_t xp23 = pack2(xv[kh + 2][kw], xv[kh + 3][kw]);
                    #pragma unroll
                    for (int g = 0; g < 8; ++g) {
                        uint64_t wg = ws2[k][g];
                        acc01[g] = ffma2(xp01, wg, acc01[g]);
                        acc23[g] = ffma2(xp23, wg, acc23[g]);
                    }
                }
            }
        }

        // Epilogue: unpack, nonlinearities, pre-combined coefficient store
        float a[4][8];
        #pragma unroll
        for (int g = 0; g < 8; ++g) {
            unpack2(acc01[g], a[0][g], a[1][g]);
            unpack2(acc23[g], a[2][g], a[3][g]);
        }

        const int wglob = w0 + tx;
        #pragma unroll
        for (int r = 0; r < 4; ++r) {
            int hglob = h0 + ty * 4 + r;
            int idx = ((b * Tn + tt) * Hn + hglob) * Wn + wglob;

            // groups: 0:kappa 1:m1 2:m2 3:Hxx 4:Hxy 5:Hyx 6:Hyy 7:tau
            float kap  = 0.99f * (1.f / (1.f + __expf(-a[r][0]))) + 0.01f;
            float kap2 = kap * kap;
            float hxx  = 0.99f * (1.f / (1.f + __expf(-a[r][3]))) + 0.01f;
            float hyy  = 0.99f * (1.f / (1.f + __expf(-a[r][6]))) + 0.01f;
            float hxys = 0.1f * (tanhf(a[r][4]) + tanhf(a[r][5]));
            float tau  = 9.9f * (1.f / (1.f + __expf(-a[r][7]))) + 0.1f;
            float Dv   = 1.f / (tau * tau);
            local_logD += -2.f * __logf(tau);

            g_params[0 * Nn + idx] = kap2 + 2.f * hxx + 2.f * hyy;   // cc
            g_params[1 * Nn + idx] =  0.5f * a[r][1] - hxx;          // ce
            g_params[2 * Nn + idx] = -0.5f * a[r][1] - hxx;          // cw
            g_params[3 * Nn + idx] =  0.5f * a[r][2] - hyy;          // cs
            g_params[4 * Nn + idx] = -0.5f * a[r][2] - hyy;          // cn
            g_params[5 * Nn + idx] = -0.25f * hxys;                  // cx
            g_params[6 * Nn + idx] = Dv;
        }
    }

    __syncthreads();
    float s = block_reduce_sum(local_logD);
    if (threadIdx.x == 0)
        g_partLogD[(blockIdx.z * 8 + blockIdx.y) * 8 + blockIdx.x] = s;
}

// ---------------------------------------------------------------------------
// Fused double stencil (unchanged from R3 — measured ~20us, DRAM-bound)
// ---------------------------------------------------------------------------
__global__ __launch_bounds__(256)
void fused_stencil_kernel(const float* __restrict__ x) {
    __shared__ float xs[36][36];
    __shared__ float ys[34][34];

    const int tid = threadIdx.x;
    const int tx  = tid & 31;
    const int ty  = tid >> 5;
    const int bt  = blockIdx.z;        // b*T + t
    const int t   = bt & (Tn - 1);
    const int h0  = blockIdx.y * 32;
    const int w0  = blockIdx.x * 32;
    const int base = bt * Hn * Wn;

    const float* up = x + base;
    for (int i = tid; i < 36 * 36; i += 256) {
        int ly = i / 36, lx = i - ly * 36;
        int gh = h0 - 2 + ly, gw = w0 - 2 + lx;
        xs[ly][lx] = ((unsigned)gh < (unsigned)Hn && (unsigned)gw < (unsigned)Wn)
                         ? up[gh * Wn + gw] : 0.f;
    }
    __syncthreads();

    for (int i = tid; i < 34 * 34; i += 256) {
        int ly = i / 34, lx = i - ly * 34;
        int gh = h0 - 1 + ly, gw = w0 - 1 + lx;
        float yv = 0.f;
        if ((unsigned)gh < (unsigned)Hn && (unsigned)gw < (unsigned)Wn) {
            int gidx = base + gh * Wn + gw;
            float c  = xs[ly + 1][lx + 1];
            float e  = xs[ly + 1][lx + 2];
            float wv = xs[ly + 1][lx + 0];
            float s  = xs[ly + 2][lx + 1];
            float n  = xs[ly + 0][lx + 1];
            float se = xs[ly + 2][lx + 2];
            float ne = xs[ly + 0][lx + 2];
            float sw = xs[ly + 2][lx + 0];
            float nw = xs[ly + 0][lx + 0];
            yv = g_params[0 * Nn + gidx] * c
               + g_params[1 * Nn + gidx] * e
               + g_params[2 * Nn + gidx] * wv
               + g_params[3 * Nn + gidx] * s
               + g_params[4 * Nn + gidx] * n
               + g_params[5 * Nn + gidx] * (se - ne - sw + nw);
        }
        ys[ly][lx] = yv;
    }
    __syncthreads();

    float local = 0.f;
    #pragma unroll
    for (int r = 0; r < 4; ++r) {
        int iy = ty * 4 + r;
        int gh = h0 + iy, gw = w0 + tx;
        int gidx = base + gh * Wn + gw;
        int ly = iy + 1, lx = tx + 1;

        float c  = ys[ly][lx];
        float e  = ys[ly][lx + 1];
        float wv = ys[ly][lx - 1];
        float s  = ys[ly + 1][lx];
        float n  = ys[ly - 1][lx];
        float se = ys[ly + 1][lx + 1];
        float ne = ys[ly - 1][lx + 1];
        float sw = ys[ly + 1][lx - 1];
        float nw = ys[ly - 1][lx - 1];

        float z = g_params[0 * Nn + gidx] * c
                + g_params[1 * Nn + gidx] * e
                + g_params[2 * Nn + gidx] * wv
                + g_params[3 * Nn + gidx] * s
                + g_params[4 * Nn + gidx] * n
                + g_params[5 * Nn + gidx] * (se - ne - sw + nw);

        float xc    = xs[iy + 2][tx + 2];
        float xprev = (t > 0) ? x[gidx - Hn * Wn] : 0.f;
        float rr = xc + z - xprev;
        local += g_params[6 * Nn + gidx] * rr * rr;
    }

    __syncthreads();
    float ssum = block_reduce_sum(local);
    if (threadIdx.x == 0)
        g_partXQX[(blockIdx.z * 8 + blockIdx.y) * 8 + blockIdx.x] = ssum;
}

// ---------------------------------------------------------------------------
// Final reduce of partials (double accumulation)
// ---------------------------------------------------------------------------
__global__ void final_kernel(float* out) {
    __shared__ double redq[32];
    __shared__ double redl[32];
    const int tid = threadIdx.x;   // 1024 threads
    double xq = (double)g_partXQX[tid] + (double)g_partXQX[tid + 1024];
    double ld = (double)g_partLogD[tid];

    #pragma unroll
    for (int o = 16; o > 0; o >>= 1) {
        xq += __shfl_down_sync(0xffffffffu, xq, o);
        ld += __shfl_down_sync(0xffffffffu, ld, o);
    }
    int lane = tid & 31, wid = tid >> 5;
    if (lane == 0) { redq[wid] = xq; redl[wid] = ld; }
    __syncthreads();
    if (wid == 0) {
        xq = redq[lane];
        ld = redl[lane];
        #pragma unroll
        for (int o = 16; o > 0; o >>= 1) {
            xq += __shfl_down_sync(0xffffffffu, xq, o);
            ld += __shfl_down_sync(0xffffffffu, ld, o);
        }
        if (lane == 0) out[0] = (float)(0.5 * (xq - ld));
    }
}

extern "C" void kernel_launch(void* const* d_in, const int* in_sizes, int n_in,
                              void* d_out, int out_size) {
    const float* x = (const float*)d_in[0];
    const float* w = (const float*)d_in[1];
    float* out = (float*)d_out;

    conv_kernel<<<dim3(8, 8, Bn * 4), 256>>>(x, w);
    fused_stencil_kernel<<<dim3(8, 8, Bn * Tn), 256>>>(x);
    final_kernel<<<1, 1024>>>(out);
}

// round 5
// speedup vs baseline: 1.1892x; 1.1892x over previous
#include <cuda_runtime.h>
#include <math.h>

#define Bn 4
#define Tn 8
#define Hn 256
#define Wn 256
#define Nn (Bn*Tn*Hn*Wn)   // 2,097,152

// params layout: 0:cc 1:ce 2:cw 3:cs 4:cn 5:cx(corner) 6:D
__device__ float g_params[7 * Nn];
__device__ float g_partLogD[1024];   // conv blocks
__device__ float g_partXQX[2048];    // fused stencil blocks

__device__ __forceinline__ float tanh_fast(float x) {
    float y; asm("tanh.approx.f32 %0, %1;" : "=f"(y) : "f"(x)); return y;
}

__device__ __forceinline__ float block_reduce_sum(float v) {
    __shared__ float red[8];
    #pragma unroll
    for (int o = 16; o > 0; o >>= 1) v += __shfl_down_sync(0xffffffffu, v, o);
    int lane = threadIdx.x & 31, wid = threadIdx.x >> 5;
    if (lane == 0) red[wid] = v;
    __syncthreads();
    if (wid == 0) {
        v = (lane < 8) ? red[lane] : 0.f;
        #pragma unroll
        for (int o = 4; o > 0; o >>= 1) v += __shfl_down_sync(0xffffffffu, v, o);
    }
    return v;  // valid on thread 0
}

// ---------------------------------------------------------------------------
// Conv 3x3 (8 -> 64 ch), scalar FFMA, register x-window, 2 t's per CTA.
// Block: 256 threads, 32x32 tile. grid (8, 8, Bn*4) = 1024 CTAs.
// ---------------------------------------------------------------------------
__global__ __launch_bounds__(256, 3)
void conv_kernel(const float* __restrict__ x, const float* __restrict__ w) {
    __shared__ float xs[8][34][34];
    __shared__ __align__(16) float ws[72][8];   // [k = ic*9+kh*3+kw][g]

    const int tid = threadIdx.x;
    const int tx  = tid & 31;
    const int ty  = tid >> 5;
    const int b   = blockIdx.z >> 2;
    const int t0  = (blockIdx.z & 3) * 2;
    const int h0  = blockIdx.y * 32;
    const int w0  = blockIdx.x * 32;

    const float* xb = x + b * Tn * Hn * Wn;
    for (int i = tid; i < 8 * 34 * 34; i += 256) {
        int ic  = i / 1156;
        int rem = i - ic * 1156;
        int ly  = rem / 34;
        int lx  = rem - ly * 34;
        int gh  = h0 - 1 + ly;
        int gw  = w0 - 1 + lx;
        float v = 0.f;
        if ((unsigned)gh < (unsigned)Hn && (unsigned)gw < (unsigned)Wn)
            v = xb[(ic * Hn + gh) * Wn + gw];
        xs[ic][ly][lx] = v;
    }

    float local_logD = 0.f;

    #pragma unroll 1
    for (int tt = t0; tt < t0 + 2; ++tt) {
        __syncthreads();
        for (int j = tid; j < 576; j += 256) {
            int k = j >> 3;
            int g = j & 7;
            ws[k][g] = w[(g * 8 + tt) * 72 + k];
        }
        __syncthreads();

        float acc[4][8];
        #pragma unroll
        for (int r = 0; r < 4; ++r)
            #pragma unroll
            for (int g = 0; g < 8; ++g) acc[r][g] = 0.f;

        #pragma unroll 1
        for (int ic = 0; ic < 8; ++ic) {
            // 6x3 x-window in registers (rows ty*4 .. ty*4+5, cols tx .. tx+2)
            float xv[6][3];
            #pragma unroll
            for (int rr = 0; rr < 6; ++rr)
                #pragma unroll
                for (int cc = 0; cc < 3; ++cc)
                    xv[rr][cc] = xs[ic][ty * 4 + rr][tx + cc];

            #pragma unroll
            for (int kh = 0; kh < 3; ++kh) {
                #pragma unroll
                for (int kw = 0; kw < 3; ++kw) {
                    const int k = ic * 9 + kh * 3 + kw;
                    float4 wa = *(const float4*)&ws[k][0];
                    float4 wb = *(const float4*)&ws[k][4];
                    #pragma unroll
                    for (int r = 0; r < 4; ++r) {
                        float xvv = xv[kh + r][kw];
                        acc[r][0] += xvv * wa.x;
                        acc[r][1] += xvv * wa.y;
                        acc[r][2] += xvv * wa.z;
                        acc[r][3] += xvv * wa.w;
                        acc[r][4] += xvv * wb.x;
                        acc[r][5] += xvv * wb.y;
                        acc[r][6] += xvv * wb.z;
                        acc[r][7] += xvv * wb.w;
                    }
                }
            }
        }

        const int wglob = w0 + tx;
        #pragma unroll
        for (int r = 0; r < 4; ++r) {
            int hglob = h0 + ty * 4 + r;
            int idx = ((b * Tn + tt) * Hn + hglob) * Wn + wglob;

            // groups: 0:kappa 1:m1 2:m2 3:Hxx 4:Hxy 5:Hyx 6:Hyy 7:tau
            float kap  = 0.99f * (1.f / (1.f + __expf(-acc[r][0]))) + 0.01f;
            float kap2 = kap * kap;
            float hxx  = 0.99f * (1.f / (1.f + __expf(-acc[r][3]))) + 0.01f;
            float hyy  = 0.99f * (1.f / (1.f + __expf(-acc[r][6]))) + 0.01f;
            float hxys = 0.1f * (tanh_fast(acc[r][4]) + tanh_fast(acc[r][5]));
            float tau  = 9.9f * (1.f / (1.f + __expf(-acc[r][7]))) + 0.1f;
            float Dv   = 1.f / (tau * tau);
            local_logD += -2.f * __logf(tau);

            g_params[0 * Nn + idx] = kap2 + 2.f * hxx + 2.f * hyy;   // cc
            g_params[1 * Nn + idx] =  0.5f * acc[r][1] - hxx;        // ce
            g_params[2 * Nn + idx] = -0.5f * acc[r][1] - hxx;        // cw
            g_params[3 * Nn + idx] =  0.5f * acc[r][2] - hyy;        // cs
            g_params[4 * Nn + idx] = -0.5f * acc[r][2] - hyy;        // cn
            g_params[5 * Nn + idx] = -0.25f * hxys;                  // cx
            g_params[6 * Nn + idx] = Dv;
        }
    }

    __syncthreads();
    float s = block_reduce_sum(local_logD);
    if (threadIdx.x == 0)
        g_partLogD[(blockIdx.z * 8 + blockIdx.y) * 8 + blockIdx.x] = s;
}

// ---------------------------------------------------------------------------
// Fused double stencil (unchanged — ~20us, DRAM-bound)
// ---------------------------------------------------------------------------
__global__ __launch_bounds__(256)
void fused_stencil_kernel(const float* __restrict__ x) {
    __shared__ float xs[36][36];
    __shared__ float ys[34][34];

    const int tid = threadIdx.x;
    const int tx  = tid & 31;
    const int ty  = tid >> 5;
    const int bt  = blockIdx.z;        // b*T + t
    const int t   = bt & (Tn - 1);
    const int h0  = blockIdx.y * 32;
    const int w0  = blockIdx.x * 32;
    const int base = bt * Hn * Wn;

    const float* up = x + base;
    for (int i = tid; i < 36 * 36; i += 256) {
        int ly = i / 36, lx = i - ly * 36;
        int gh = h0 - 2 + ly, gw = w0 - 2 + lx;
        xs[ly][lx] = ((unsigned)gh < (unsigned)Hn && (unsigned)gw < (unsigned)Wn)
                         ? up[gh * Wn + gw] : 0.f;
    }
    __syncthreads();

    for (int i = tid; i < 34 * 34; i += 256) {
        int ly = i / 34, lx = i - ly * 34;
        int gh = h0 - 1 + ly, gw = w0 - 1 + lx;
        float yv = 0.f;
        if ((unsigned)gh < (unsigned)Hn && (unsigned)gw < (unsigned)Wn) {
            int gidx = base + gh * Wn + gw;
            float c  = xs[ly + 1][lx + 1];
            float e  = xs[ly + 1][lx + 2];
            float wv = xs[ly + 1][lx + 0];
            float s  = xs[ly + 2][lx + 1];
            float n  = xs[ly + 0][lx + 1];
            float se = xs[ly + 2][lx + 2];
            float ne = xs[ly + 0][lx + 2];
            float sw = xs[ly + 2][lx + 0];
            float nw = xs[ly + 0][lx + 0];
            yv = g_params[0 * Nn + gidx] * c
               + g_params[1 * Nn + gidx] * e
               + g_params[2 * Nn + gidx] * wv
               + g_params[3 * Nn + gidx] * s
               + g_params[4 * Nn + gidx] * n
               + g_params[5 * Nn + gidx] * (se - ne - sw + nw);
        }
        ys[ly][lx] = yv;
    }
    __syncthreads();

    float local = 0.f;
    #pragma unroll
    for (int r = 0; r < 4; ++r) {
        int iy = ty * 4 + r;
        int gh = h0 + iy, gw = w0 + tx;
        int gidx = base + gh * Wn + gw;
        int ly = iy + 1, lx = tx + 1;

        float c  = ys[ly][lx];
        float e  = ys[ly][lx + 1];
        float wv = ys[ly][lx - 1];
        float s  = ys[ly + 1][lx];
        float n  = ys[ly - 1][lx];
        float se = ys[ly + 1][lx + 1];
        float ne = ys[ly - 1][lx + 1];
        float sw = ys[ly + 1][lx - 1];
        float nw = ys[ly - 1][lx - 1];

        float z = g_params[0 * Nn + gidx] * c
                + g_params[1 * Nn + gidx] * e
                + g_params[2 * Nn + gidx] * wv
                + g_params[3 * Nn + gidx] * s
                + g_params[4 * Nn + gidx] * n
                + g_params[5 * Nn + gidx] * (se - ne - sw + nw);

        float xc    = xs[iy + 2][tx + 2];
        float xprev = (t > 0) ? x[gidx - Hn * Wn] : 0.f;
        float rr = xc + z - xprev;
        local += g_params[6 * Nn + gidx] * rr * rr;
    }

    __syncthreads();
    float ssum = block_reduce_sum(local);
    if (threadIdx.x == 0)
        g_partXQX[(blockIdx.z * 8 + blockIdx.y) * 8 + blockIdx.x] = ssum;
}

// ---------------------------------------------------------------------------
// Final reduce of partials (double accumulation)
// ---------------------------------------------------------------------------
__global__ void final_kernel(float* out) {
    __shared__ double redq[32];
    __shared__ double redl[32];
    const int tid = threadIdx.x;   // 1024 threads
    double xq = (double)g_partXQX[tid] + (double)g_partXQX[tid + 1024];
    double ld = (double)g_partLogD[tid];

    #pragma unroll
    for (int o = 16; o > 0; o >>= 1) {
        xq += __shfl_down_sync(0xffffffffu, xq, o);
        ld += __shfl_down_sync(0xffffffffu, ld, o);
    }
    int lane = tid & 31, wid = tid >> 5;
    if (lane == 0) { redq[wid] = xq; redl[wid] = ld; }
    __syncthreads();
    if (wid == 0) {
        xq = redq[lane];
        ld = redl[lane];
        #pragma unroll
        for (int o = 16; o > 0; o >>= 1) {
            xq += __shfl_down_sync(0xffffffffu, xq, o);
            ld += __shfl_down_sync(0xffffffffu, ld, o);
        }
        if (lane == 0) out[0] = (float)(0.5 * (xq - ld));
    }
}

extern "C" void kernel_launch(void* const* d_in, const int* in_sizes, int n_in,
                              void* d_out, int out_size) {
    const float* x = (const float*)d_in[0];
    const float* w = (const float*)d_in[1];
    float* out = (float*)d_out;

    conv_kernel<<<dim3(8, 8, Bn * 4), 256>>>(x, w);
    fused_stencil_kernel<<<dim3(8, 8, Bn * Tn), 256>>>(x);
    final_kernel<<<1, 1024>>>(out);
}

// round 6
// speedup vs baseline: 1.5540x; 1.3068x over previous
#include <cuda_runtime.h>
#include <math.h>
#include <stdint.h>

#define Bn 4
#define Tn 8
#define Hn 256
#define Wn 256
#define Nn (Bn*Tn*Hn*Wn)   // 2,097,152

// params layout: 0:cc 1:ce 2:cw 3:cs 4:cn 5:cx(corner) 6:D
__device__ float g_params[7 * Nn];
__device__ float g_partLogD[2048];   // conv CTAs
__device__ float g_partXQX[2048];    // fused stencil CTAs

__device__ __forceinline__ float tanh_fast(float x) {
    float y; asm("tanh.approx.f32 %0, %1;" : "=f"(y) : "f"(x)); return y;
}
__device__ __forceinline__ uint32_t f2tf32(float f) {
    uint32_t u; asm("cvt.rna.tf32.f32 %0, %1;" : "=r"(u) : "f"(f)); return u;
}
__device__ __forceinline__ void mma_tf32(float c[4],
                                         uint32_t a0, uint32_t a1, uint32_t a2, uint32_t a3,
                                         uint32_t b0, uint32_t b1) {
    asm("mma.sync.aligned.m16n8k8.row.col.f32.tf32.tf32.f32 "
        "{%0,%1,%2,%3}, {%4,%5,%6,%7}, {%8,%9}, {%0,%1,%2,%3};"
        : "+f"(c[0]), "+f"(c[1]), "+f"(c[2]), "+f"(c[3])
        : "r"(a0), "r"(a1), "r"(a2), "r"(a3), "r"(b0), "r"(b1));
}

__device__ __forceinline__ float block_reduce_sum(float v) {
    __shared__ float red[8];
    #pragma unroll
    for (int o = 16; o > 0; o >>= 1) v += __shfl_down_sync(0xffffffffu, v, o);
    int lane = threadIdx.x & 31, wid = threadIdx.x >> 5;
    if (lane == 0) red[wid] = v;
    __syncthreads();
    if (wid == 0) {
        v = (lane < 8) ? red[lane] : 0.f;
        #pragma unroll
        for (int o = 4; o > 0; o >>= 1) v += __shfl_down_sync(0xffffffffu, v, o);
    }
    return v;  // valid on thread 0
}

// ---------------------------------------------------------------------------
// Conv 3x3 (8 -> 64 ch) as implicit GEMM on tensor cores (tf32 mma.sync).
// CTA: 256 thr / 8 warps. Tile: 128 pixels (row segment) x 64 oc, K = 72.
// K-order: k = tap*8 + ic  (tap = kh*3+kw), so A-fragment cols = ic.
// grid (2 w-segs, 256 h, 4 b) = 2048 CTAs.
// ---------------------------------------------------------------------------
__global__ __launch_bounds__(256)
void conv_mma_kernel(const float* __restrict__ x, const float* __restrict__ w) {
    __shared__ uint32_t xs[3][8][136];     // [row kh][ic][col], tf32 bits, zero-padded
    __shared__ uint32_t Wsm[72 * 72];      // [k][oc], width 72 for bank spread

    const int tid  = threadIdx.x;
    const int lane = tid & 31;
    const int wid  = tid >> 5;
    const int seg  = blockIdx.x;           // 0..1
    const int h    = blockIdx.y;           // 0..255
    const int b    = blockIdx.z;           // 0..3
    const int w0   = seg * 128;

    // ---- stage weights (tf32) ----
    for (int j = tid; j < 72 * 64; j += 256) {
        int k  = j >> 6;          // 0..71
        int oc = j & 63;
        int tap = k >> 3;
        int ic  = k & 7;
        Wsm[k * 72 + oc] = f2tf32(w[oc * 72 + ic * 9 + tap]);
    }

    // ---- stage x slab: rows h-1..h+1, cols w0-1..w0+128, 8 ic (tf32) ----
    const float* xb = x + b * Tn * Hn * Wn;
    for (int i = tid; i < 3 * 8 * 130; i += 256) {
        int r   = i / 1040;
        int rem = i - r * 1040;
        int ic  = rem / 130;
        int col = rem - ic * 130;
        int gh  = h - 1 + r;
        int gw  = w0 - 1 + col;
        float v = 0.f;
        if ((unsigned)gh < (unsigned)Hn && (unsigned)gw < (unsigned)Wn)
            v = xb[(ic * Hn + gh) * Wn + gw];
        xs[r][ic][col] = f2tf32(v);
    }
    __syncthreads();

    // ---- GEMM: each warp: m16 (pixels) x n64 (oc), K=72 ----
    const int q  = lane & 3;          // 0..3
    const int m0 = (wid << 4) + (lane >> 2);   // this thread's base pixel (row 0 of frag)

    float acc[8][4];
    #pragma unroll
    for (int n = 0; n < 8; ++n)
        #pragma unroll
        for (int c = 0; c < 4; ++c) acc[n][c] = 0.f;

    #pragma unroll
    for (int tap = 0; tap < 9; ++tap) {
        const int kh = tap / 3, kw = tap % 3;
        uint32_t a0 = xs[kh][q    ][m0 + kw];
        uint32_t a1 = xs[kh][q    ][m0 + 8 + kw];
        uint32_t a2 = xs[kh][q + 4][m0 + kw];
        uint32_t a3 = xs[kh][q + 4][m0 + 8 + kw];

        const uint32_t* Wr0 = &Wsm[(tap * 8 + q)     * 72 + (lane >> 2)];
        const uint32_t* Wr1 = &Wsm[(tap * 8 + q + 4) * 72 + (lane >> 2)];
        #pragma unroll
        for (int n = 0; n < 8; ++n) {
            uint32_t b0 = Wr0[n * 8];
            uint32_t b1 = Wr1[n * 8];
            mma_tf32(acc[n], a0, a1, a2, a3, b0, b1);
        }
    }

    // ---- epilogue: thread owns pixels {m0, m0+8}, t in {2q, 2q+1}, all 8 groups
    float local_logD = 0.f;
    #pragma unroll
    for (int pi = 0; pi < 2; ++pi) {
        int pix = m0 + 8 * pi;
        int wglob = w0 + pix;
        #pragma unroll
        for (int ti = 0; ti < 2; ++ti) {
            int t = 2 * q + ti;
            int cidx = 2 * pi + ti;
            float a0v = acc[0][cidx];   // kappa
            float a1v = acc[1][cidx];   // m1
            float a2v = acc[2][cidx];   // m2
            float a3v = acc[3][cidx];   // Hxx
            float a4v = acc[4][cidx];   // Hxy
            float a5v = acc[5][cidx];   // Hyx
            float a6v = acc[6][cidx];   // Hyy
            float a7v = acc[7][cidx];   // tau

            float kap  = 0.99f * (1.f / (1.f + __expf(-a0v))) + 0.01f;
            float kap2 = kap * kap;
            float hxx  = 0.99f * (1.f / (1.f + __expf(-a3v))) + 0.01f;
            float hyy  = 0.99f * (1.f / (1.f + __expf(-a6v))) + 0.01f;
            float hxys = 0.1f * (tanh_fast(a4v) + tanh_fast(a5v));
            float tau  = 9.9f * (1.f / (1.f + __expf(-a7v))) + 0.1f;
            float Dv   = 1.f / (tau * tau);
            local_logD += -2.f * __logf(tau);

            int idx = ((b * Tn + t) * Hn + h) * Wn + wglob;
            g_params[0 * Nn + idx] = kap2 + 2.f * hxx + 2.f * hyy;   // cc
            g_params[1 * Nn + idx] =  0.5f * a1v - hxx;              // ce
            g_params[2 * Nn + idx] = -0.5f * a1v - hxx;              // cw
            g_params[3 * Nn + idx] =  0.5f * a2v - hyy;              // cs
            g_params[4 * Nn + idx] = -0.5f * a2v - hyy;              // cn
            g_params[5 * Nn + idx] = -0.25f * hxys;                  // cx
            g_params[6 * Nn + idx] = Dv;
        }
    }

    __syncthreads();
    float s = block_reduce_sum(local_logD);
    if (tid == 0)
        g_partLogD[(blockIdx.z * 256 + blockIdx.y) * 2 + blockIdx.x] = s;
}

// ---------------------------------------------------------------------------
// Fused double stencil (unchanged — ~20us, DRAM-bound)
// ---------------------------------------------------------------------------
__global__ __launch_bounds__(256)
void fused_stencil_kernel(const float* __restrict__ x) {
    __shared__ float xs[36][36];
    __shared__ float ys[34][34];

    const int tid = threadIdx.x;
    const int tx  = tid & 31;
    const int ty  = tid >> 5;
    const int bt  = blockIdx.z;        // b*T + t
    const int t   = bt & (Tn - 1);
    const int h0  = blockIdx.y * 32;
    const int w0  = blockIdx.x * 32;
    const int base = bt * Hn * Wn;

    const float* up = x + base;
    for (int i = tid; i < 36 * 36; i += 256) {
        int ly = i / 36, lx = i - ly * 36;
        int gh = h0 - 2 + ly, gw = w0 - 2 + lx;
        xs[ly][lx] = ((unsigned)gh < (unsigned)Hn && (unsigned)gw < (unsigned)Wn)
                         ? up[gh * Wn + gw] : 0.f;
    }
    __syncthreads();

    for (int i = tid; i < 34 * 34; i += 256) {
        int ly = i / 34, lx = i - ly * 34;
        int gh = h0 - 1 + ly, gw = w0 - 1 + lx;
        float yv = 0.f;
        if ((unsigned)gh < (unsigned)Hn && (unsigned)gw < (unsigned)Wn) {
            int gidx = base + gh * Wn + gw;
            float c  = xs[ly + 1][lx + 1];
            float e  = xs[ly + 1][lx + 2];
            float wv = xs[ly + 1][lx + 0];
            float s  = xs[ly + 2][lx + 1];
            float n  = xs[ly + 0][lx + 1];
            float se = xs[ly + 2][lx + 2];
            float ne = xs[ly + 0][lx + 2];
            float sw = xs[ly + 2][lx + 0];
            float nw = xs[ly + 0][lx + 0];
            yv = g_params[0 * Nn + gidx] * c
               + g_params[1 * Nn + gidx] * e
               + g_params[2 * Nn + gidx] * wv
               + g_params[3 * Nn + gidx] * s
               + g_params[4 * Nn + gidx] * n
               + g_params[5 * Nn + gidx] * (se - ne - sw + nw);
        }
        ys[ly][lx] = yv;
    }
    __syncthreads();

    float local = 0.f;
    #pragma unroll
    for (int r = 0; r < 4; ++r) {
        int iy = ty * 4 + r;
        int gh = h0 + iy, gw = w0 + tx;
        int gidx = base + gh * Wn + gw;
        int ly = iy + 1, lx = tx + 1;

        float c  = ys[ly][lx];
        float e  = ys[ly][lx + 1];
        float wv = ys[ly][lx - 1];
        float s  = ys[ly + 1][lx];
        float n  = ys[ly - 1][lx];
        float se = ys[ly + 1][lx + 1];
        float ne = ys[ly - 1][lx + 1];
        float sw = ys[ly + 1][lx - 1];
        float nw = ys[ly - 1][lx - 1];

        float z = g_params[0 * Nn + gidx] * c
                + g_params[1 * Nn + gidx] * e
                + g_params[2 * Nn + gidx] * wv
                + g_params[3 * Nn + gidx] * s
                + g_params[4 * Nn + gidx] * n
                + g_params[5 * Nn + gidx] * (se - ne - sw + nw);

        float xc    = xs[iy + 2][tx + 2];
        float xprev = (t > 0) ? x[gidx - Hn * Wn] : 0.f;
        float rr = xc + z - xprev;
        local += g_params[6 * Nn + gidx] * rr * rr;
    }

    __syncthreads();
    float ssum = block_reduce_sum(local);
    if (threadIdx.x == 0)
        g_partXQX[(blockIdx.z * 8 + blockIdx.y) * 8 + blockIdx.x] = ssum;
}

// ---------------------------------------------------------------------------
// Final reduce of partials (double accumulation)
// ---------------------------------------------------------------------------
__global__ void final_kernel(float* out) {
    __shared__ double redq[32];
    __shared__ double redl[32];
    const int tid = threadIdx.x;   // 1024 threads
    double xq = (double)g_partXQX[tid]  + (double)g_partXQX[tid + 1024];
    double ld = (double)g_partLogD[tid] + (double)g_partLogD[tid + 1024];

    #pragma unroll
    for (int o = 16; o > 0; o >>= 1) {
        xq += __shfl_down_sync(0xffffffffu, xq, o);
        ld += __shfl_down_sync(0xffffffffu, ld, o);
    }
    int lane = tid & 31, wid = tid >> 5;
    if (lane == 0) { redq[wid] = xq; redl[wid] = ld; }
    __syncthreads();
    if (wid == 0) {
        xq = redq[lane];
        ld = redl[lane];
        #pragma unroll
        for (int o = 16; o > 0; o >>= 1) {
            xq += __shfl_down_sync(0xffffffffu, xq, o);
            ld += __shfl_down_sync(0xffffffffu, ld, o);
        }
        if (lane == 0) out[0] = (float)(0.5 * (xq - ld));
    }
}

extern "C" void kernel_launch(void* const* d_in, const int* in_sizes, int n_in,
                              void* d_out, int out_size) {
    const float* x = (const float*)d_in[0];
    const float* w = (const float*)d_in[1];
    float* out = (float*)d_out;

    conv_mma_kernel<<<dim3(2, 256, Bn), 256>>>(x, w);
    fused_stencil_kernel<<<dim3(8, 8, Bn * Tn), 256>>>(x);
    final_kernel<<<1, 1024>>>(out);
}